// round 12
// baseline (speedup 1.0000x reference)
#include <cuda_runtime.h>
#include <cuda_fp16.h>
#include <cstdint>

#define NT 256
#define ROWS 128
#define NCHUNK 8
// smem byte offsets
#define SM_A    0         // 128 rows x 264 fp16 (stride 528B) = 67584
#define SM_W1   67584     // 2 bufs x (64n x 264k fp16) = 2 x 33792
#define W1BUF   33792
#define SM_W2   135168    // 2 bufs x (128n x 72k fp16, stride 144B) = 2 x 18432
#define W2BUF   18432
#define SM_TOTAL 172032

__device__ float g_agg[50000 * 128];
// weight images: fp16, chunk-contiguous
__device__ __align__(16) __half g_w1m[8 * 64 * 264];
__device__ __align__(16) __half g_w2m[8 * 128 * 72];
__device__ __align__(16) __half g_w1u[8 * 64 * 264];
__device__ __align__(16) __half g_w2u[8 * 128 * 72];

__device__ __forceinline__ uint32_t smem_u32(const void* p) {
    uint32_t a;
    asm("{ .reg .u64 t; cvta.to.shared.u64 t, %1; cvt.u32.u64 %0, t; }" : "=r"(a) : "l"(p));
    return a;
}
__device__ __forceinline__ void ldm4(uint32_t addr, uint32_t* r) {
    asm volatile("ldmatrix.sync.aligned.m8n8.x4.shared.b16 {%0,%1,%2,%3}, [%4];"
                 : "=r"(r[0]), "=r"(r[1]), "=r"(r[2]), "=r"(r[3]) : "r"(addr));
}
__device__ __forceinline__ void mma_f16(float* c, const uint32_t* a,
                                        uint32_t b0, uint32_t b1) {
    asm volatile(
        "mma.sync.aligned.m16n8k16.row.col.f32.f16.f16.f32 "
        "{%0,%1,%2,%3}, {%4,%5,%6,%7}, {%8,%9}, {%0,%1,%2,%3};"
        : "+f"(c[0]), "+f"(c[1]), "+f"(c[2]), "+f"(c[3])
        : "r"(a[0]), "r"(a[1]), "r"(a[2]), "r"(a[3]), "r"(b0), "r"(b1));
}
__device__ __forceinline__ void cp16(uint32_t dst, const void* src) {
    asm volatile("cp.async.cg.shared.global [%0], [%1], 16;" :: "r"(dst), "l"(src));
}
__device__ __forceinline__ uint32_t h2bits(__half2 v) {
    return *reinterpret_cast<uint32_t*>(&v);
}
__device__ __forceinline__ void red_v2(float* p, float a, float b) {
    asm volatile("red.global.add.v2.f32 [%0], {%1,%2};"
                 :: "l"(p), "f"(a), "f"(b) : "memory");
}

// ---- merged prep: zero agg + zero out + 4 weight images ----
// blocks: agg [0,6250) | out [6250,12500) | w1m [12500,13012) | w2m [13012,13268)
//         | w1u [13268,13780) | w2u [13780,14036)
__global__ void prep_all(const float* __restrict__ W1m, const float* __restrict__ W2m,
                         const float* __restrict__ W1u, const float* __restrict__ W2u,
                         float* __restrict__ agg, float* __restrict__ outz) {
    int b = blockIdx.x, tid = threadIdx.x;
    if (b < 6250) {
        ((float4*)agg)[b * NT + tid] = make_float4(0.f, 0.f, 0.f, 0.f);
    } else if (b < 12500) {
        ((float4*)outz)[(b - 6250) * NT + tid] = make_float4(0.f, 0.f, 0.f, 0.f);
    } else if (b < 13268) {
        if (b < 13012) {  // w1m: [8 c(n64)][64n][264k]
            int idx = (b - 12500) * NT + tid;
            int k = idx >> 9, n = idx & 511;
            g_w1m[(n >> 6) * 16896 + (n & 63) * 264 + k] = __float2half_rn(W1m[idx]);
        } else {          // w2m: [8 c(k64)][128n][72k]
            int idx = (b - 13012) * NT + tid;
            int k = idx >> 7, n = idx & 127;
            g_w2m[(k >> 6) * 9216 + n * 72 + (k & 63)] = __float2half_rn(W2m[idx]);
        }
    } else {
        if (b < 13780) {  // w1u
            int idx = (b - 13268) * NT + tid;
            int k = idx >> 9, n = idx & 511;
            g_w1u[(n >> 6) * 16896 + (n & 63) * 264 + k] = __float2half_rn(W1u[idx]);
        } else {          // w2u
            int idx = (b - 13780) * NT + tid;
            int k = idx >> 7, n = idx & 127;
            g_w2u[(k >> 6) * 9216 + n * 72 + (k & 63)] = __float2half_rn(W2u[idx]);
        }
    }
}

// prefetch chunk c (W1 + W2) into buffer c&1, one commit group
__device__ __forceinline__ void prefetch_chunk(uint32_t sb, int c,
        const __half* w1, const __half* w2, int tid) {
    const char* s1 = ((const char*)w1) + c * 33792;
    uint32_t d1 = sb + SM_W1 + (uint32_t)(c & 1) * W1BUF;
#pragma unroll
    for (int j = 0; j < 9; ++j) {
        int idx = tid + j * NT;
        if (idx < 2112) cp16(d1 + idx * 16, s1 + idx * 16);
    }
    const char* s2 = ((const char*)w2) + c * 18432;
    uint32_t d2 = sb + SM_W2 + (uint32_t)(c & 1) * W2BUF;
#pragma unroll
    for (int j = 0; j < 5; ++j) {
        int idx = tid + j * NT;
        if (idx < 1152) cp16(d2 + idx * 16, s2 + idx * 16);
    }
    asm volatile("cp.async.commit_group;");
}

// Fused 2-layer MLP, 128 rows/CTA. GEMM1 -> register relu/pack -> GEMM2 (K-split
// across the 2 n-warps, partials combined via red.global). One barrier per chunk.
// Warps: 4m(32 rows) x 2n. Output always via red (out pre-zeroed for node path).
template <bool IS_EDGE>
__global__ __launch_bounds__(NT, 1)
void mlp_mma(const float* __restrict__ x, const float* __restrict__ second,
             const int* __restrict__ eidx,
             const __half* __restrict__ w1, const __half* __restrict__ w2,
             const float* __restrict__ b1, const float* __restrict__ b2,
             float* __restrict__ out, int M, int E) {
    extern __shared__ __align__(16) unsigned char smem[];
    const uint32_t sb = smem_u32(smem);
    const int tid = threadIdx.x;
    const int lane = tid & 31;
    const int wid = tid >> 5;
    const int wm = wid & 3, wn = wid >> 2;
    const int rowbase = blockIdx.x * ROWS;

    prefetch_chunk(sb, 0, w1, w2, tid);

    // ---- gather A = [feat_i(128) | feat_j(128)] -> fp16 smem ----
    {
        int r = tid >> 1, half = tid & 1;
        int row = rowbase + r;
        const float* src;
        if (IS_EDGE) {
            int e = (row < E) ? row : 0;
            int node = half ? eidx[e] : eidx[E + e];   // half0 = i, half1 = j
            src = x + (size_t)node * 128;
        } else {
            int rr = (row < M) ? row : 0;
            src = (half ? second : x) + (size_t)rr * 128;
        }
        uint32_t abase = sb + SM_A + (uint32_t)(r * 528 + half * 256);
#pragma unroll
        for (int jj = 0; jj < 32; ++jj) {
            float4 v = *(const float4*)(src + jj * 4);
            uint32_t h0 = h2bits(__float22half2_rn(make_float2(v.x, v.y)));
            uint32_t h1 = h2bits(__float22half2_rn(make_float2(v.z, v.w)));
            asm volatile("st.shared.v2.b32 [%0], {%1,%2};"
                         :: "r"(abase + jj * 8), "r"(h0), "r"(h1) : "memory");
        }
    }

    // lane base addresses
    const uint32_t aB0 = sb + SM_A +
        (uint32_t)((wm * 32 + (lane & 15)) * 528 + ((lane >> 4) & 1) * 16);
    const uint32_t aB1 = aB0 + 16 * 528;
    const uint32_t bOff = (uint32_t)((wn * 32 + (lane & 7) + ((lane >> 4) & 1) * 8) * 528 +
                                     ((lane >> 3) & 1) * 16);
    const uint32_t w2lane = (uint32_t)(((lane & 7) + ((lane >> 4) & 1) * 8) * 144 +
                                       ((lane >> 3) & 1) * 16);

    float acc2[128];
#pragma unroll
    for (int i = 0; i < 128; ++i) acc2[i] = 0.f;

    const int rsub = lane >> 2;        // 0..7
    const int cc = (lane & 3) * 2;

    for (int c = 0; c < NCHUNK; ++c) {
        asm volatile("cp.async.wait_group 0;");   // chunk c in smem
        __syncthreads();                           // + prev buffers free
        if (c + 1 < NCHUNK) prefetch_chunk(sb, c + 1, w1, w2, tid);

        const uint32_t w1b = sb + SM_W1 + (uint32_t)(c & 1) * W1BUF;
        const uint32_t w2b = sb + SM_W2 + (uint32_t)(c & 1) * W2BUF;

        // ---- GEMM1: acc1[32 rows x 32 cols], K=256 ----
        float acc1[32];
#pragma unroll
        for (int i = 0; i < 32; ++i) acc1[i] = 0.f;
#pragma unroll
        for (int s = 0; s < 16; ++s) {
            uint32_t a0[4], a1[4], b0[4], b1r[4];
            ldm4(aB0 + s * 32, a0);
            ldm4(aB1 + s * 32, a1);
            ldm4(w1b + bOff + s * 32, b0);
            ldm4(w1b + bOff + 16 * 528 + s * 32, b1r);
            mma_f16(acc1 + 0,  a0, b0[0], b0[1]);
            mma_f16(acc1 + 4,  a0, b0[2], b0[3]);
            mma_f16(acc1 + 8,  a0, b1r[0], b1r[1]);
            mma_f16(acc1 + 12, a0, b1r[2], b1r[3]);
            mma_f16(acc1 + 16, a1, b0[0], b0[1]);
            mma_f16(acc1 + 20, a1, b0[2], b0[3]);
            mma_f16(acc1 + 24, a1, b1r[0], b1r[1]);
            mma_f16(acc1 + 28, a1, b1r[2], b1r[3]);
        }

        // ---- register epilogue: relu(acc1+b1) -> GEMM2 A-fragments ----
        uint32_t hf[2][2][4];   // [mf][s2][reg]
#pragma unroll
        for (int mf = 0; mf < 2; ++mf) {
#pragma unroll
            for (int s2 = 0; s2 < 2; ++s2) {
#pragma unroll
                for (int qq = 0; qq < 2; ++qq) {
                    int q = s2 * 2 + qq;
                    const float* ac = acc1 + mf * 16 + q * 4;
                    int gcol = c * 64 + wn * 32 + q * 8 + cc;
                    float ba = __ldg(b1 + gcol), bb = __ldg(b1 + gcol + 1);
                    float v0 = fmaxf(ac[0] + ba, 0.f);
                    float v1 = fmaxf(ac[1] + bb, 0.f);
                    float v2 = fmaxf(ac[2] + ba, 0.f);
                    float v3 = fmaxf(ac[3] + bb, 0.f);
                    hf[mf][s2][qq * 2 + 0] = h2bits(__float22half2_rn(make_float2(v0, v1)));
                    hf[mf][s2][qq * 2 + 1] = h2bits(__float22half2_rn(make_float2(v2, v3)));
                }
            }
        }

        // ---- GEMM2 (K-split): acc2 += H[:, wn*32..+32] @ W2[wn-slice, 0:128] ----
#pragma unroll
        for (int s2 = 0; s2 < 2; ++s2) {
            uint32_t kbyte = (uint32_t)((wn * 32 + s2 * 16) * 2);
#pragma unroll
            for (int p = 0; p < 8; ++p) {
                uint32_t bw[4];
                ldm4(w2b + w2lane + (uint32_t)(p * 16 * 144) + kbyte, bw);
                mma_f16(acc2 + p * 8 + 0,      hf[0][s2], bw[0], bw[1]);
                mma_f16(acc2 + p * 8 + 4,      hf[0][s2], bw[2], bw[3]);
                mma_f16(acc2 + 64 + p * 8 + 0, hf[1][s2], bw[0], bw[1]);
                mma_f16(acc2 + 64 + p * 8 + 4, hf[1][s2], bw[2], bw[3]);
            }
        }
    }

    // ---- final epilogue: red_v2(out, acc2 (+ b2 from wn==0 only)) ----
#pragma unroll
    for (int mf = 0; mf < 2; ++mf) {
        int e0 = rowbase + wm * 32 + mf * 16 + rsub;
        int e1 = e0 + 8;
        int lim = IS_EDGE ? E : M;
        int tgt0 = e0, tgt1 = e1;
        if (IS_EDGE) {
            tgt0 = (e0 < E) ? eidx[E + e0] : 0;
            tgt1 = (e1 < E) ? eidx[E + e1] : 0;
        }
#pragma unroll
        for (int p = 0; p < 8; ++p) {
#pragma unroll
            for (int t = 0; t < 2; ++t) {
                const float* ac = acc2 + mf * 64 + p * 8 + t * 4;
                int col = p * 16 + t * 8 + cc;
                float ba = 0.f, bb = 0.f;
                if (wn == 0) { ba = __ldg(b2 + col); bb = __ldg(b2 + col + 1); }
                if (e0 < lim) red_v2(out + (size_t)tgt0 * 128 + col, ac[0] + ba, ac[1] + bb);
                if (e1 < lim) red_v2(out + (size_t)tgt1 * 128 + col, ac[2] + ba, ac[3] + bb);
            }
        }
    }
}

extern "C" void kernel_launch(void* const* d_in, const int* in_sizes, int n_in,
                              void* d_out, int out_size) {
    const float* x   = (const float*)d_in[0];
    const int* eidx  = (const int*)d_in[2];   // JAX demotes int64 -> int32
    const float* W1m = (const float*)d_in[3];
    const float* b1m = (const float*)d_in[4];
    const float* W2m = (const float*)d_in[5];
    const float* b2m = (const float*)d_in[6];
    const float* W1u = (const float*)d_in[7];
    const float* b1u = (const float*)d_in[8];
    const float* W2u = (const float*)d_in[9];
    const float* b2u = (const float*)d_in[10];
    float* out = (float*)d_out;

    int N = in_sizes[0] / 128;
    int E = in_sizes[2] / 2;

    float* agg; cudaGetSymbolAddress((void**)&agg, g_agg);
    __half *w1m, *w2m, *w1u, *w2u;
    cudaGetSymbolAddress((void**)&w1m, g_w1m);
    cudaGetSymbolAddress((void**)&w2m, g_w2m);
    cudaGetSymbolAddress((void**)&w1u, g_w1u);
    cudaGetSymbolAddress((void**)&w2u, g_w2u);

    cudaFuncSetAttribute((const void*)mlp_mma<true>,
                         cudaFuncAttributeMaxDynamicSharedMemorySize, SM_TOTAL);
    cudaFuncSetAttribute((const void*)mlp_mma<false>,
                         cudaFuncAttributeMaxDynamicSharedMemorySize, SM_TOTAL);

    prep_all<<<14036, NT>>>(W1m, W2m, W1u, W2u, agg, out);

    mlp_mma<true><<<(E + ROWS - 1) / ROWS, NT, SM_TOTAL>>>(
        x, x, eidx, w1m, w2m, b1m, b2m, agg, E, E);

    mlp_mma<false><<<(N + ROWS - 1) / ROWS, NT, SM_TOTAL>>>(
        x, agg, nullptr, w1u, w2u, b1u, b2u, out, N, 0);
}

// round 13
// speedup vs baseline: 1.1282x; 1.1282x over previous
#include <cuda_runtime.h>
#include <cuda_fp16.h>
#include <cstdint>

#define NT 256
#define ROWS 192
#define NCHUNK 8
// smem byte offsets
#define SM_A    0         // 192 rows x 264 fp16 (stride 528B) = 101376
#define SM_W1   101376    // single buf: 64n x 264k = 33792
#define SM_W2   135168    // 2 bufs x (128n x 72k, stride 144B) = 2 x 18432
#define W2BUF   18432
#define SM_H    172032    // 192 x 72 fp16 (stride 144B) = 27648
#define SM_TOTAL 199680

__device__ float g_agg[50000 * 128];
// weight images: fp16 hi only, chunk-contiguous
__device__ __align__(16) __half g_w1m[8 * 64 * 264];
__device__ __align__(16) __half g_w2m[8 * 128 * 72];
__device__ __align__(16) __half g_w1u[8 * 64 * 264];
__device__ __align__(16) __half g_w2u[8 * 128 * 72];

__device__ __forceinline__ uint32_t smem_u32(const void* p) {
    uint32_t a;
    asm("{ .reg .u64 t; cvta.to.shared.u64 t, %1; cvt.u32.u64 %0, t; }" : "=r"(a) : "l"(p));
    return a;
}
__device__ __forceinline__ void ldm4(uint32_t addr, uint32_t* r) {
    asm volatile("ldmatrix.sync.aligned.m8n8.x4.shared.b16 {%0,%1,%2,%3}, [%4];"
                 : "=r"(r[0]), "=r"(r[1]), "=r"(r[2]), "=r"(r[3]) : "r"(addr));
}
__device__ __forceinline__ void mma_f16(float* c, const uint32_t* a,
                                        uint32_t b0, uint32_t b1) {
    asm volatile(
        "mma.sync.aligned.m16n8k16.row.col.f32.f16.f16.f32 "
        "{%0,%1,%2,%3}, {%4,%5,%6,%7}, {%8,%9}, {%0,%1,%2,%3};"
        : "+f"(c[0]), "+f"(c[1]), "+f"(c[2]), "+f"(c[3])
        : "r"(a[0]), "r"(a[1]), "r"(a[2]), "r"(a[3]), "r"(b0), "r"(b1));
}
__device__ __forceinline__ void cp16(uint32_t dst, const void* src) {
    asm volatile("cp.async.cg.shared.global [%0], [%1], 16;" :: "r"(dst), "l"(src));
}
__device__ __forceinline__ uint32_t h2bits(__half2 v) {
    return *reinterpret_cast<uint32_t*>(&v);
}
__device__ __forceinline__ void red_v2(float* p, float a, float b) {
    asm volatile("red.global.add.v2.f32 [%0], {%1,%2};"
                 :: "l"(p), "f"(a), "f"(b) : "memory");
}

// ---- merged prep: zero agg + 4 hi-only weight images ----
// blocks: zero [0,6250) | w1m [6250,6762) | w2m [6762,7018) | w1u [7018,7530) | w2u [7530,7786)
__global__ void prep_all(const float* __restrict__ W1m, const float* __restrict__ W2m,
                         const float* __restrict__ W1u, const float* __restrict__ W2u,
                         float* __restrict__ agg) {
    int b = blockIdx.x, tid = threadIdx.x;
    if (b < 6250) {
        ((float4*)agg)[b * NT + tid] = make_float4(0.f, 0.f, 0.f, 0.f);
    } else if (b < 6762 || (b >= 7018 && b < 7530)) {   // W1 [256k x 512n] -> [8 c(n64)][64n][264k]
        bool msg = (b < 6762);
        const float* W = msg ? W1m : W1u;
        __half* hi = msg ? g_w1m : g_w1u;
        int idx = (b - (msg ? 6250 : 7018)) * NT + tid;
        int k = idx >> 9, n = idx & 511;
        hi[(n >> 6) * 16896 + (n & 63) * 264 + k] = __float2half_rn(W[idx]);
    } else {                                            // W2 [512k x 128n] -> [8 c(k64)][128n][72k]
        bool msg = (b < 7018);
        const float* W = msg ? W2m : W2u;
        __half* hi = msg ? g_w2m : g_w2u;
        int idx = (b - (msg ? 6762 : 7530)) * NT + tid;
        int k = idx >> 7, n = idx & 127;
        hi[(k >> 6) * 9216 + n * 72 + (k & 63)] = __float2half_rn(W[idx]);
    }
}

__device__ __forceinline__ void prefetch_w1(uint32_t sb, int c,
                                            const __half* w1, int tid) {
    const char* s = ((const char*)w1) + c * 33792;
#pragma unroll
    for (int j = 0; j < 9; ++j) {
        int idx = tid + j * NT;
        if (idx < 2112) cp16(sb + SM_W1 + idx * 16, s + idx * 16);
    }
    asm volatile("cp.async.commit_group;");
}
__device__ __forceinline__ void prefetch_w2(uint32_t sb, int c,
                                            const __half* w2, int tid) {
    const char* s = ((const char*)w2) + c * 18432;
    uint32_t d = sb + SM_W2 + (uint32_t)(c & 1) * W2BUF;
#pragma unroll
    for (int j = 0; j < 5; ++j) {
        int idx = tid + j * NT;
        if (idx < 1152) cp16(d + idx * 16, s + idx * 16);
    }
    asm volatile("cp.async.commit_group;");
}

// Fused 2-layer MLP, 192 rows/CTA, single-term fp16 mma.sync.
// W1 single-buffered (committed 1 chunk ahead), W2 double-buffered (2 ahead).
// 3 barriers/chunk, no mid-chunk fetch wait. Warps: 4m(48 rows) x 2n.
template <bool IS_EDGE>
__global__ __launch_bounds__(NT, 1)
void mlp_mma(const float* __restrict__ x, const float* __restrict__ second,
             const int* __restrict__ eidx,
             const __half* __restrict__ w1, const __half* __restrict__ w2,
             const float* __restrict__ b1, const float* __restrict__ b2,
             float* __restrict__ out, int M, int E) {
    extern __shared__ __align__(16) unsigned char smem[];
    const uint32_t sb = smem_u32(smem);
    const int tid = threadIdx.x;
    const int lane = tid & 31;
    const int wid = tid >> 5;
    const int wm = wid & 3, wn = wid >> 2;
    const int rowbase = blockIdx.x * ROWS;

    // commit order: W1(0), W2(0), W2(1)
    prefetch_w1(sb, 0, w1, tid);
    prefetch_w2(sb, 0, w2, tid);
    prefetch_w2(sb, 1, w2, tid);

    // ---- gather A = [feat_i(128) | feat_j(128)] -> fp16 smem ----
    for (int idx = tid; idx < ROWS * 2; idx += NT) {
        int r = idx >> 1, half = idx & 1;
        int row = rowbase + r;
        const float* src;
        if (IS_EDGE) {
            int e = (row < E) ? row : 0;
            int node = half ? eidx[e] : eidx[E + e];   // half0 = i, half1 = j
            src = x + (size_t)node * 128;
        } else {
            int rr = (row < M) ? row : 0;
            src = (half ? second : x) + (size_t)rr * 128;
        }
        uint32_t abase = sb + SM_A + (uint32_t)(r * 528 + half * 256);
#pragma unroll
        for (int jj = 0; jj < 32; ++jj) {
            float4 v = *(const float4*)(src + jj * 4);
            uint32_t h0 = h2bits(__float22half2_rn(make_float2(v.x, v.y)));
            uint32_t h1 = h2bits(__float22half2_rn(make_float2(v.z, v.w)));
            asm volatile("st.shared.v2.b32 [%0], {%1,%2};"
                         :: "r"(abase + jj * 8), "r"(h0), "r"(h1) : "memory");
        }
    }

    // ldmatrix base addresses (3 m-frags per warp)
    uint32_t aB[3], hB[3];
#pragma unroll
    for (int mf = 0; mf < 3; ++mf) {
        aB[mf] = sb + SM_A +
            (uint32_t)((wm * 48 + mf * 16 + (lane & 15)) * 528 + ((lane >> 4) & 1) * 16);
        hB[mf] = sb + SM_H +
            (uint32_t)((wm * 48 + mf * 16 + (lane & 15)) * 144 + ((lane >> 4) & 1) * 16);
    }
    const uint32_t bB0 = sb + SM_W1 +
        (uint32_t)((wn * 32 + (lane & 7) + ((lane >> 4) & 1) * 8) * 528 +
                   ((lane >> 3) & 1) * 16);
    const uint32_t bB1 = bB0 + 16 * 528;
    uint32_t w2Off[4];
#pragma unroll
    for (int p = 0; p < 4; ++p)
        w2Off[p] = (uint32_t)((wn * 64 + p * 16 + (lane & 7) + ((lane >> 4) & 1) * 8) * 144 +
                              ((lane >> 3) & 1) * 16);

    float acc2[96];
#pragma unroll
    for (int i = 0; i < 96; ++i) acc2[i] = 0.f;

    const int rsub = lane >> 2;        // 0..7
    const int cc = (lane & 3) * 2;

    for (int c = 0; c < NCHUNK; ++c) {
        // W1(c) and W2(c) both committed >= 1 full group before the most recent
        if (c == NCHUNK - 1) asm volatile("cp.async.wait_group 0;");
        else                 asm volatile("cp.async.wait_group 1;");
        __syncthreads();

        // ---- GEMM1: acc1[192 x 64chunk], K=256, single term ----
        float acc1[48];
#pragma unroll
        for (int i = 0; i < 48; ++i) acc1[i] = 0.f;
#pragma unroll
        for (int s = 0; s < 16; ++s) {
            uint32_t a0[4], a1[4], a2[4], b0[4], b1r[4];
            ldm4(aB[0] + s * 32, a0);
            ldm4(aB[1] + s * 32, a1);
            ldm4(aB[2] + s * 32, a2);
            ldm4(bB0 + s * 32, b0);
            ldm4(bB1 + s * 32, b1r);
            mma_f16(acc1 + 0,  a0, b0[0], b0[1]);
            mma_f16(acc1 + 4,  a0, b0[2], b0[3]);
            mma_f16(acc1 + 8,  a0, b1r[0], b1r[1]);
            mma_f16(acc1 + 12, a0, b1r[2], b1r[3]);
            mma_f16(acc1 + 16, a1, b0[0], b0[1]);
            mma_f16(acc1 + 20, a1, b0[2], b0[3]);
            mma_f16(acc1 + 24, a1, b1r[0], b1r[1]);
            mma_f16(acc1 + 28, a1, b1r[2], b1r[3]);
            mma_f16(acc1 + 32, a2, b0[0], b0[1]);
            mma_f16(acc1 + 36, a2, b0[2], b0[3]);
            mma_f16(acc1 + 40, a2, b1r[0], b1r[1]);
            mma_f16(acc1 + 44, a2, b1r[2], b1r[3]);
        }

        // ---- epilogue: relu(acc1 + b1) -> fp16 H smem ----
#pragma unroll
        for (int mf = 0; mf < 3; ++mf) {
#pragma unroll
            for (int nq = 0; nq < 4; ++nq) {
                const float* ac = acc1 + mf * 16 + nq * 4;
                int gcol = c * 64 + wn * 32 + nq * 8 + cc;
                float ba = __ldg(b1 + gcol), bb = __ldg(b1 + gcol + 1);
                float v00 = fmaxf(ac[0] + ba, 0.f);
                float v01 = fmaxf(ac[1] + bb, 0.f);
                float v10 = fmaxf(ac[2] + ba, 0.f);
                float v11 = fmaxf(ac[3] + bb, 0.f);
                uint32_t p0 = h2bits(__float22half2_rn(make_float2(v00, v01)));
                uint32_t p1 = h2bits(__float22half2_rn(make_float2(v10, v11)));
                int hcol = wn * 32 + nq * 8 + cc;
                int r0 = wm * 48 + mf * 16 + rsub;
                uint32_t a0 = sb + SM_H + (uint32_t)(r0 * 144 + hcol * 2);
                asm volatile("st.shared.b32 [%0], %1;" :: "r"(a0), "r"(p0) : "memory");
                asm volatile("st.shared.b32 [%0], %1;" :: "r"(a0 + 8 * 144), "r"(p1) : "memory");
            }
        }
        __syncthreads();   // H visible; W1 slab fully consumed

        if (c + 1 < NCHUNK) prefetch_w1(sb, c + 1, w1, tid);  // full-chunk lead

        // ---- GEMM2: acc2 += H[192x64] @ W2[64x128], W2 buf c&1 (already resident) ----
        const uint32_t w2b = sb + SM_W2 + (uint32_t)(c & 1) * W2BUF;
#pragma unroll
        for (int s = 0; s < 4; ++s) {
            uint32_t h0[4], h1[4], h2[4];
            ldm4(hB[0] + s * 32, h0);
            ldm4(hB[1] + s * 32, h1);
            ldm4(hB[2] + s * 32, h2);
#pragma unroll
            for (int p = 0; p < 4; ++p) {
                uint32_t bw[4];
                ldm4(w2b + w2Off[p] + s * 32, bw);
                mma_f16(acc2 + p * 8 + 0,  h0, bw[0], bw[1]);
                mma_f16(acc2 + p * 8 + 4,  h0, bw[2], bw[3]);
                mma_f16(acc2 + 32 + p * 8 + 0, h1, bw[0], bw[1]);
                mma_f16(acc2 + 32 + p * 8 + 4, h1, bw[2], bw[3]);
                mma_f16(acc2 + 64 + p * 8 + 0, h2, bw[0], bw[1]);
                mma_f16(acc2 + 64 + p * 8 + 4, h2, bw[2], bw[3]);
            }
        }
        __syncthreads();   // W2 buf (c&1) free for c+2
        if (c + 2 < NCHUNK) prefetch_w2(sb, c + 2, w2, tid);   // two-chunk lead
    }

    // ---- final epilogue: out = acc2 + b2 (v2 reductions / stores) ----
#pragma unroll
    for (int mf = 0; mf < 3; ++mf) {
        int e0 = rowbase + wm * 48 + mf * 16 + rsub;
        int e1 = e0 + 8;
        int tgt0 = 0, tgt1 = 0;
        if (IS_EDGE) {
            tgt0 = (e0 < E) ? eidx[E + e0] : 0;
            tgt1 = (e1 < E) ? eidx[E + e1] : 0;
        }
#pragma unroll
        for (int p = 0; p < 4; ++p) {
#pragma unroll
            for (int t = 0; t < 2; ++t) {
                const float* ac = acc2 + mf * 32 + p * 8 + t * 4;
                int col = wn * 64 + p * 16 + t * 8 + cc;
                float ba = __ldg(b2 + col), bb = __ldg(b2 + col + 1);
                float v00 = ac[0] + ba, v01 = ac[1] + bb;
                float v10 = ac[2] + ba, v11 = ac[3] + bb;
                if (IS_EDGE) {
                    if (e0 < E) red_v2(out + (size_t)tgt0 * 128 + col, v00, v01);
                    if (e1 < E) red_v2(out + (size_t)tgt1 * 128 + col, v10, v11);
                } else {
                    if (e0 < M) *(float2*)(out + (size_t)e0 * 128 + col) = make_float2(v00, v01);
                    if (e1 < M) *(float2*)(out + (size_t)e1 * 128 + col) = make_float2(v10, v11);
                }
            }
        }
    }
}

extern "C" void kernel_launch(void* const* d_in, const int* in_sizes, int n_in,
                              void* d_out, int out_size) {
    const float* x   = (const float*)d_in[0];
    const int* eidx  = (const int*)d_in[2];   // JAX demotes int64 -> int32
    const float* W1m = (const float*)d_in[3];
    const float* b1m = (const float*)d_in[4];
    const float* W2m = (const float*)d_in[5];
    const float* b2m = (const float*)d_in[6];
    const float* W1u = (const float*)d_in[7];
    const float* b1u = (const float*)d_in[8];
    const float* W2u = (const float*)d_in[9];
    const float* b2u = (const float*)d_in[10];
    float* out = (float*)d_out;

    int N = in_sizes[0] / 128;
    int E = in_sizes[2] / 2;

    float* agg; cudaGetSymbolAddress((void**)&agg, g_agg);
    __half *w1m, *w2m, *w1u, *w2u;
    cudaGetSymbolAddress((void**)&w1m, g_w1m);
    cudaGetSymbolAddress((void**)&w2m, g_w2m);
    cudaGetSymbolAddress((void**)&w1u, g_w1u);
    cudaGetSymbolAddress((void**)&w2u, g_w2u);

    cudaFuncSetAttribute((const void*)mlp_mma<true>,
                         cudaFuncAttributeMaxDynamicSharedMemorySize, SM_TOTAL);
    cudaFuncSetAttribute((const void*)mlp_mma<false>,
                         cudaFuncAttributeMaxDynamicSharedMemorySize, SM_TOTAL);

    prep_all<<<7786, NT>>>(W1m, W2m, W1u, W2u, agg);

    mlp_mma<true><<<(E + ROWS - 1) / ROWS, NT, SM_TOTAL>>>(
        x, x, eidx, w1m, w2m, b1m, b2m, agg, E, E);

    mlp_mma<false><<<(N + ROWS - 1) / ROWS, NT, SM_TOTAL>>>(
        x, agg, nullptr, w1u, w2u, b1u, b2u, out, N, 0);
}